// round 13
// baseline (speedup 1.0000x reference)
#include <cuda_runtime.h>

#define NN 50000
#define DD 128
#define EE 800000
#define EPSV 1e-5f
#define MTILES 391  // ceil(50000/128)
#define SCANB 49    // ceil(50000/1024)

// ---------------- scratch ----------------
__device__ __align__(16) float g_q [NN*DD];
__device__ __align__(16) float g_k [NN*DD];
__device__ __align__(16) float g_v [NN*DD];
__device__ __align__(16) float g_sp[NN*DD];
__device__ __align__(16) float g_h [NN*DD];
__device__ __align__(16) float g_t [NN*2*DD];
__device__ int   g_cnt[NN];          // zero at module load; self-cleaned each run
__device__ int   g_rowptr[NN+1];
__device__ int   g_cur[NN];
__device__ int   g_srcs[EE];
__device__ int   g_part[SCANB];
__device__ int   g_ctr1, g_ctr2;     // cumulative grid-barrier counters (never reset)
__device__ int   g_bnctr[2];
__device__ __align__(16) float g_sums [4*DD];   // self-cleaned by bnstats
__device__ __align__(16) float g_scale[2*DD];
__device__ __align__(16) float g_shift[2*DD];

// ---------------- fused CSR build: hist + scan in one kernel ----------------
// 49 blocks x 1024 threads, all co-resident (49 << 148 SMs).
// Grid barriers: cumulative counters (each run adds exactly SCANB arrivals, so
// target = (old/SCANB + 1)*SCANB works across graph replays without reset).
// All cross-block reads use atomicAdd(,0) (L2, non-hoistable); every thread
// fences before its block's arrival so RED histogram updates are visible.
__global__ void histscan_kernel(const int* __restrict__ dst) {
    __shared__ int sm[1024];
    __shared__ int sbase;
    const int b = blockIdx.x, t = threadIdx.x;
    const int gid = b * 1024 + t;
    const int NT = SCANB * 1024;  // 50176

    // phase 1: histogram
    for (int e = gid; e < EE; e += NT)
        atomicAdd(&g_cnt[dst[e]], 1);
    __threadfence();
    __syncthreads();
    if (t == 0) {
        int my = atomicAdd(&g_ctr1, 1);
        int target = (my / SCANB + 1) * SCANB;
        while (atomicAdd(&g_ctr1, 0) < target) { }
    }
    __syncthreads();

    // phase 2: block-local inclusive scan of this block's g_cnt slice
    int c = (gid < NN) ? atomicAdd(&g_cnt[gid], 0) : 0;
    sm[t] = c;
    __syncthreads();
    for (int off = 1; off < 1024; off <<= 1) {
        int v = (t >= off) ? sm[t - off] : 0;
        __syncthreads();
        sm[t] += v;
        __syncthreads();
    }
    // publish block total + barrier 2 (same thread publishes and arrives:
    // per-thread ordering atomicExch -> fence -> arrive is guaranteed)
    if (t == 1023) {
        atomicExch(&g_part[b], sm[1023]);
        __threadfence();
        int my = atomicAdd(&g_ctr2, 1);
        int target = (my / SCANB + 1) * SCANB;
        while (atomicAdd(&g_ctr2, 0) < target) { }
    }
    __syncthreads();

    // phase 3: base = prefix over earlier blocks, write rowptr/cur, self-clean
    if (t == 0) {
        int base = 0;
        for (int j = 0; j < b; j++) base += atomicAdd(&g_part[j], 0);
        sbase = base;
    }
    __syncthreads();
    int base = sbase;
    if (gid < NN) {
        int ex = base + sm[t] - c;
        g_rowptr[gid] = ex;
        g_cur[gid]    = ex;
        g_cnt[gid]    = 0;   // ready for next replay
    }
    if (b == SCANB - 1 && t == 1023) g_rowptr[NN] = base + sm[1023];
}

__global__ void scatter_kernel(const int* __restrict__ src, const int* __restrict__ dst) {
    for (int e = blockIdx.x * blockDim.x + threadIdx.x; e < EE; e += gridDim.x * blockDim.x) {
        int pos = atomicAdd(&g_cur[dst[e]], 1);
        g_srcs[pos] = src[e];
    }
}

// ---------------- attention: one warp per dst node, online softmax (R11 exact) ----
__global__ void attn_kernel(const float* __restrict__ q, const float* __restrict__ k,
                            const float* __restrict__ v, float* __restrict__ sp)
{
    int warp = (blockIdx.x * blockDim.x + threadIdx.x) >> 5;
    int lane = threadIdx.x & 31;
    if (warp >= NN) return;
    int beg = g_rowptr[warp];
    int end = g_rowptr[warp + 1];

    float4 qv = *(const float4*)(q + (size_t)warp * DD + lane * 4);

    float m = -1e30f, den = 0.f;
    float4 acc = make_float4(0.f, 0.f, 0.f, 0.f);

    for (int i = beg; i < end; i++) {
        int s = g_srcs[i];
        float4 kv = *(const float4*)(k + (size_t)s * DD + lane * 4);
        float d = qv.x * kv.x + qv.y * kv.y + qv.z * kv.z + qv.w * kv.w;
        #pragma unroll
        for (int o = 16; o; o >>= 1) d += __shfl_xor_sync(0xffffffffu, d, o);
        d *= 0.08838834764831845f;

        float mnew = fmaxf(m, d);
        float r = __expf(m - mnew);
        float p = __expf(d - mnew);
        den = den * r + p;
        float4 vv = *(const float4*)(v + (size_t)s * DD + lane * 4);
        acc.x = acc.x * r + p * vv.x;
        acc.y = acc.y * r + p * vv.y;
        acc.z = acc.z * r + p * vv.z;
        acc.w = acc.w * r + p * vv.w;
        m = mnew;
    }

    float inv = (end > beg) ? (1.f / den) : 0.f;
    float* spp = sp + (size_t)warp * DD + lane * 4;
    float4 spv = *(const float4*)spp;
    float4 o;
    o.x = acc.x * inv + spv.x;
    o.y = acc.y * inv + spv.y;
    o.z = acc.z * inv + spv.z;
    o.w = acc.w * inv + spv.w;
    *(float4*)spp = o;
}

// ---------------- tf32 tensor-core GEMM: cp.async pipelined, 2 CTAs/SM ----------
struct P4 {
    const float* W[4];
    const float* B[4];
    float*       C[4];
};

__device__ __forceinline__ float tf32r(float x) {
    unsigned u;
    asm("cvt.rna.tf32.f32 %0, %1;" : "=r"(u) : "f"(x));
    return __uint_as_float(u);
}

__device__ __forceinline__ void mma8(float* c, const unsigned* a, const unsigned* b) {
    asm volatile(
        "mma.sync.aligned.m16n8k8.row.col.f32.tf32.tf32.f32 "
        "{%0,%1,%2,%3}, {%4,%5,%6,%7}, {%8,%9}, {%0,%1,%2,%3};\n"
        : "+f"(c[0]), "+f"(c[1]), "+f"(c[2]), "+f"(c[3])
        : "r"(a[0]), "r"(a[1]), "r"(a[2]), "r"(a[3]), "r"(b[0]), "r"(b[1]));
}

template<int KC, int ZMODE, int BNB, int BNADD>
__global__ void __launch_bounds__(256, 2)
gemm_tc(const float* __restrict__ A, P4 p, const float* __restrict__ add,
        int M, int ldW, int relu)
{
    constexpr int K   = KC * 64;
    constexpr int NCH = KC * 2;
    extern __shared__ float sms[];
    float* Bs     = sms;
    float* bias_s = sms + K * 128 + 8192;
    unsigned abBase[2];
    abBase[0] = (unsigned)__cvta_generic_to_shared(sms + K * 128);
    abBase[1] = abBase[0] + 16384;

    const int tid  = threadIdx.x;
    const int lane = tid & 31;
    const int warp = tid >> 5;
    const int wm = warp & 1;
    const int wn = warp >> 1;

    int z, m0, mstep, colOff;
    if (ZMODE == 1)      { z = blockIdx.x & 3; colOff = 0;                      m0 = blockIdx.x >> 2; mstep = gridDim.x >> 2; }
    else if (ZMODE == 2) { z = 0;              colOff = (blockIdx.x & 1) * 128; m0 = blockIdx.x >> 1; mstep = gridDim.x >> 1; }
    else                 { z = 0;              colOff = 0;                      m0 = blockIdx.x;      mstep = gridDim.x; }

    const float* W    = p.W[ZMODE == 1 ? z : 0];
    const float* bias = p.B[ZMODE == 1 ? z : 0] + colOff;
    float*       C    = p.C[ZMODE == 1 ? z : 0];
    const int ldC = ldW;

    int mi_p = m0, kc_p = 0;
    int mi_c = m0, kc_c = 0;
    auto issueA = [&](int mi, int kc, int bi) {
        int rowBase = mi * 128;
        #pragma unroll
        for (int it = 0; it < 4; it++) {
            int idx = it * 256 + tid;
            int row = idx >> 3;
            int c   = idx & 7;
            int grow = rowBase + row;
            const float* src = A + (size_t)grow * K + kc * 32 + c * 4;
            unsigned dst = abBase[bi] + (row << 7) + ((c ^ (row & 7)) << 4);
            int sz = (grow < M) ? 16 : 0;
            asm volatile("cp.async.cg.shared.global [%0], [%1], 16, %2;"
                         :: "r"(dst), "l"(src), "r"(sz));
        }
    };
    auto adv = [](int& mi, int& kc, int step) {
        if (++kc == NCH) { kc = 0; mi += step; }
    };

    issueA(mi_p, kc_p, 0);
    adv(mi_p, kc_p, mstep);
    asm volatile("cp.async.commit_group;");

    #pragma unroll 4
    for (int it = 0; it < K / 8; it++) {
        int k  = it * 8 + (tid >> 5);
        int n0 = (tid & 31) * 4;
        float4 w = *(const float4*)(W + (size_t)k * ldW + colOff + n0);
        float s = BNB ? g_scale[k] : 1.f;
        float4 r;
        r.x = tf32r(w.x * s); r.y = tf32r(w.y * s);
        r.z = tf32r(w.z * s); r.w = tf32r(w.w * s);
        int kq = k >> 2, k3 = k & 3;
        int base = kq * 512 + k3 * 128 + (n0 & ~31) + ((n0 + 8 * k3) & 31);
        *(float4*)(Bs + base) = r;
    }
    if (tid < 128) {
        float b = bias[tid];
        if (BNB) {
            float a = 0.f;
            #pragma unroll 8
            for (int k = 0; k < K; k++)
                a += g_shift[k] * W[(size_t)k * ldW + colOff + tid];
            b += a;
        }
        bias_s[tid] = b;
    }
    __syncthreads();

    const int rl   = (lane & 7) + ((lane >> 3) & 1) * 8;
    const int cbit = lane >> 4;
    int innerj[4];
    #pragma unroll
    for (int j = 0; j < 4; j++)
        innerj[j] = ((j << 3) + (lane >> 2) + ((lane & 3) << 3)) & 31;

    float acc[4][4][4];
    int buf = 0;

    while (mi_c < MTILES) {
        if (mi_p < MTILES) {
            issueA(mi_p, kc_p, buf ^ 1);
            adv(mi_p, kc_p, mstep);
        }
        asm volatile("cp.async.commit_group;");
        asm volatile("cp.async.wait_group 1;");
        __syncthreads();

        if (kc_c == 0) {
            #pragma unroll
            for (int i = 0; i < 4; i++)
                #pragma unroll
                for (int j = 0; j < 4; j++)
                    #pragma unroll
                    for (int r = 0; r < 4; r++) acc[i][j][r] = 0.f;
        }

        const unsigned ab = abBase[buf];
        #pragma unroll
        for (int kt = 0; kt < 4; kt++) {
            unsigned af[4][4], bf[4][2];
            #pragma unroll
            for (int i = 0; i < 4; i++) {
                int mt = wm * 4 + i;
                unsigned addr = ab + ((mt * 16 + rl) << 7)
                              + ((((kt << 1) + cbit) ^ (lane & 7)) << 4);
                asm volatile("ldmatrix.sync.aligned.m8n8.x4.shared.b16 {%0,%1,%2,%3}, [%4];"
                             : "=r"(af[i][0]), "=r"(af[i][1]), "=r"(af[i][2]), "=r"(af[i][3])
                             : "r"(addr));
                #pragma unroll
                for (int q = 0; q < 4; q++)
                    asm("cvt.rna.tf32.f32 %0, %0;" : "+r"(af[i][q]));
            }
            int kq0 = (kc_c * 8 + kt * 2) * 512 + (lane & 3) * 128 + wn * 32;
            #pragma unroll
            for (int j = 0; j < 4; j++) {
                bf[j][0] = __float_as_uint(Bs[kq0 + innerj[j]]);
                bf[j][1] = __float_as_uint(Bs[kq0 + 512 + innerj[j]]);
            }
            #pragma unroll
            for (int i = 0; i < 4; i++)
                #pragma unroll
                for (int j = 0; j < 4; j++)
                    mma8(acc[i][j], af[i], bf[j]);
        }

        if (kc_c == NCH - 1) {
            int rowBase = mi_c * 128;
            #pragma unroll
            for (int i = 0; i < 4; i++) {
                int r0 = rowBase + wm * 64 + i * 16 + (lane >> 2);
                #pragma unroll
                for (int j = 0; j < 4; j++) {
                    int cl = wn * 32 + j * 8 + (lane & 3) * 2;
                    int cg = colOff + cl;
                    float2 bb = *(const float2*)&bias_s[cl];
                    #pragma unroll
                    for (int hh = 0; hh < 2; hh++) {
                        int r = r0 + hh * 8;
                        if (r >= M) continue;
                        float2 o;
                        o.x = acc[i][j][hh * 2 + 0] + bb.x;
                        o.y = acc[i][j][hh * 2 + 1] + bb.y;
                        if (add) {
                            float2 ad = *(const float2*)(add + (size_t)r * ldC + cg);
                            if (BNADD) {
                                ad.x = ad.x * g_scale[cg]     + g_shift[cg];
                                ad.y = ad.y * g_scale[cg + 1] + g_shift[cg + 1];
                            }
                            o.x += ad.x; o.y += ad.y;
                        }
                        if (relu) { o.x = fmaxf(o.x, 0.f); o.y = fmaxf(o.y, 0.f); }
                        *(float2*)(C + (size_t)r * ldC + cg) = o;
                    }
                }
            }
        }
        __syncthreads();
        buf ^= 1;
        adv(mi_c, kc_c, mstep);
    }
}

// ---------------- BatchNorm: stats + last-block finalize + self-clean ----------
__global__ void bnstats_kernel(const float* __restrict__ h,
                               const float* __restrict__ g, const float* __restrict__ be,
                               int which) {
    int c = threadIdx.x;
    float s = 0.f, s2 = 0.f;
    for (int r = blockIdx.x; r < NN; r += gridDim.x) {
        float vv = h[(size_t)r * DD + c];
        s += vv;
        s2 += vv * vv;
    }
    atomicAdd(&g_sums[which * 2 * DD + c], s);
    atomicAdd(&g_sums[which * 2 * DD + DD + c], s2);

    __shared__ bool last;
    __threadfence();
    if (threadIdx.x == 0) {
        int t = atomicAdd(&g_bnctr[which], 1);
        last = (t == (int)gridDim.x - 1);
    }
    __syncthreads();
    if (last) {
        float ssum = g_sums[which * 2 * DD + c];
        float qsum = g_sums[which * 2 * DD + DD + c];
        float mu  = ssum / (float)NN;
        float var = qsum / (float)NN - mu * mu;
        float sc = g[c] * rsqrtf(var + EPSV);
        g_scale[which * DD + c] = sc;
        g_shift[which * DD + c] = be[c] - mu * sc;
        g_sums[which * 2 * DD + c]      = 0.f;   // self-clean for next replay
        g_sums[which * 2 * DD + DD + c] = 0.f;
        if (threadIdx.x == 0) g_bnctr[which] = 0;
    }
}

__global__ void bnapply_kernel(float* __restrict__ h, int which) {
    const int total = NN * DD / 4;
    for (int i = blockIdx.x * blockDim.x + threadIdx.x; i < total; i += gridDim.x * blockDim.x) {
        float4 vv = ((float4*)h)[i];
        int cb = (i & 31) << 2;
        float4 sc = *(const float4*)&g_scale[which * DD + cb];
        float4 sh = *(const float4*)&g_shift[which * DD + cb];
        vv.x = vv.x * sc.x + sh.x;
        vv.y = vv.y * sc.y + sh.y;
        vv.z = vv.z * sc.z + sh.z;
        vv.w = vv.w * sc.w + sh.w;
        ((float4*)h)[i] = vv;
    }
}

// ---------------- launch ----------------
extern "C" void kernel_launch(void* const* d_in, const int* in_sizes, int n_in,
                              void* d_out, int out_size)
{
    const float* x  = (const float*)d_in[0];
    const int*   ei = (const int*)  d_in[1];
    const float *Wq = (const float*)d_in[2],  *bq = (const float*)d_in[3];
    const float *Wk = (const float*)d_in[4],  *bk = (const float*)d_in[5];
    const float *Wv = (const float*)d_in[6],  *bv = (const float*)d_in[7];
    const float *Ws = (const float*)d_in[8],  *bs = (const float*)d_in[9];
    const float *WO = (const float*)d_in[10], *bO = (const float*)d_in[11];
    const float *W1 = (const float*)d_in[12], *b1 = (const float*)d_in[13];
    const float *W2 = (const float*)d_in[14], *b2 = (const float*)d_in[15];
    const float *g1 = (const float*)d_in[16], *be1 = (const float*)d_in[17];
    const float *g2 = (const float*)d_in[18], *be2 = (const float*)d_in[19];
    float* out = (float*)d_out;

    const int* src = ei;
    const int* dst = ei + EE;

    float *q, *k, *v, *sp, *h, *t;
    cudaGetSymbolAddress((void**)&q,  g_q);
    cudaGetSymbolAddress((void**)&k,  g_k);
    cudaGetSymbolAddress((void**)&v,  g_v);
    cudaGetSymbolAddress((void**)&sp, g_sp);
    cudaGetSymbolAddress((void**)&h,  g_h);
    cudaGetSymbolAddress((void**)&t,  g_t);

    const int SM2 = 2 * 64 * 128 * 4 + 32768 + 512;   // KC=2: 2 CTAs/SM
    const int SM4 = 4 * 64 * 128 * 4 + 32768 + 512;   // KC=4: 1 CTA/SM
    cudaFuncSetAttribute(gemm_tc<2,1,0,0>, cudaFuncAttributeMaxDynamicSharedMemorySize, SM2);
    cudaFuncSetAttribute(gemm_tc<2,0,0,0>, cudaFuncAttributeMaxDynamicSharedMemorySize, SM2);
    cudaFuncSetAttribute(gemm_tc<2,2,1,0>, cudaFuncAttributeMaxDynamicSharedMemorySize, SM2);
    cudaFuncSetAttribute(gemm_tc<4,0,0,1>, cudaFuncAttributeMaxDynamicSharedMemorySize, SM4);

    cudaStream_t s1;
    cudaEvent_t ev0, ev1;
    cudaStreamCreateWithFlags(&s1, cudaStreamNonBlocking);
    cudaEventCreateWithFlags(&ev0, cudaEventDisableTiming);
    cudaEventCreateWithFlags(&ev1, cudaEventDisableTiming);

    // fork point (before any work on main)
    cudaEventRecord(ev0, 0);
    cudaStreamWaitEvent(s1, ev0, 0);

    // launch 0 (main): fused Q/K/V/S projections — overlaps CSR build
    {
        P4 p;
        p.W[0] = Wq; p.B[0] = bq; p.C[0] = q;
        p.W[1] = Wk; p.B[1] = bk; p.C[1] = k;
        p.W[2] = Wv; p.B[2] = bv; p.C[2] = v;
        p.W[3] = Ws; p.B[3] = bs; p.C[3] = sp;
        gemm_tc<2,1,0,0><<<296, 256, SM2>>>(x, p, nullptr, NN, 128, 0);
    }

    // launches 1-2 (s1): CSR build
    histscan_kernel<<<SCANB, 1024, 0, s1>>>(dst);
    scatter_kernel<<<512, 256, 0, s1>>>(src, dst);
    cudaEventRecord(ev1, s1);

    // join
    cudaStreamWaitEvent(0, ev1, 0);

    // launch 3 (main): attention — the ncu-profiled slot
    attn_kernel<<<(NN * 32 + 255) / 256, 256>>>(q, k, v, sp);

    // h = sp @ WO + bO + x
    {
        P4 p = {};
        p.W[0] = WO; p.B[0] = bO; p.C[0] = h;
        gemm_tc<2,0,0,0><<<296, 256, SM2>>>(sp, p, x, NN, 128, 0);
    }

    // BN1 stats + finalize (apply folded into FFN1 / FFN2)
    bnstats_kernel<<<256, 128>>>(h, g1, be1, 0);

    // FFN1: t = relu(BN1(h) @ W1 + b1)
    {
        P4 p = {};
        p.W[0] = W1; p.B[0] = b1; p.C[0] = t;
        gemm_tc<2,2,1,0><<<296, 256, SM2>>>(h, p, nullptr, NN, 256, 1);
    }
    // FFN2: out = t @ W2 + b2 + BN1(h)
    {
        P4 p = {};
        p.W[0] = W2; p.B[0] = b2; p.C[0] = out;
        gemm_tc<4,0,0,1><<<148, 256, SM4>>>(t, p, h, NN, 128, 0);
    }

    // BN2 stats + finalize, then apply
    bnstats_kernel<<<256, 128>>>(out, g2, be2, 1);
    bnapply_kernel<<<512, 256>>>(out, 1);
}

// round 14
// speedup vs baseline: 1.0329x; 1.0329x over previous
#include <cuda_runtime.h>

#define NN 50000
#define DD 128
#define EE 800000
#define EPSV 1e-5f
#define MTILES 391  // ceil(50000/128)
#define SCANB 49    // ceil(50000/1024)

// ---------------- scratch ----------------
__device__ __align__(16) float g_q [NN*DD];
__device__ __align__(16) float g_k [NN*DD];
__device__ __align__(16) float g_v [NN*DD];
__device__ __align__(16) float g_sp[NN*DD];
__device__ __align__(16) float g_h [NN*DD];
__device__ __align__(16) float g_t [NN*2*DD];
__device__ int   g_cnt[NN];
__device__ int   g_rowptr[NN+1];
__device__ int   g_cur[NN];
__device__ int   g_srcs[EE];
__device__ int   g_part[SCANB];
__device__ int   g_bnctr[2];
__device__ __align__(16) float g_sums [4*DD];
__device__ __align__(16) float g_scale[2*DD];
__device__ __align__(16) float g_shift[2*DD];

// ---------------- CSR build (R11 proven) ----------------
__global__ void zero_kernel() {
    int i = blockIdx.x * blockDim.x + threadIdx.x;
    if (i < NN) g_cnt[i] = 0;
    if (i < 4*DD) g_sums[i] = 0.f;
    if (i < 2) g_bnctr[i] = 0;
}

__global__ void hist_kernel(const int* __restrict__ dst) {
    for (int e = blockIdx.x * blockDim.x + threadIdx.x; e < EE; e += gridDim.x * blockDim.x)
        atomicAdd(&g_cnt[dst[e]], 1);
}

__global__ void scanA_kernel() {
    __shared__ int sm[1024];
    int idx = blockIdx.x * 1024 + threadIdx.x;
    sm[threadIdx.x] = (idx < NN) ? g_cnt[idx] : 0;
    __syncthreads();
    #pragma unroll
    for (int off = 512; off; off >>= 1) {
        if (threadIdx.x < off) sm[threadIdx.x] += sm[threadIdx.x + off];
        __syncthreads();
    }
    if (threadIdx.x == 0) g_part[blockIdx.x] = sm[0];
}

__global__ void scanB_kernel() {
    __shared__ int sm[1024];
    int b = blockIdx.x, t = threadIdx.x;
    int idx = b * 1024 + t;
    int c = (idx < NN) ? g_cnt[idx] : 0;
    sm[t] = c;
    __syncthreads();
    for (int off = 1; off < 1024; off <<= 1) {
        int v = (t >= off) ? sm[t - off] : 0;
        __syncthreads();
        sm[t] += v;
        __syncthreads();
    }
    int base = 0;
    for (int j = 0; j < b; j++) base += g_part[j];
    if (idx < NN) {
        int ex = base + sm[t] - c;
        g_rowptr[idx] = ex;
        g_cur[idx]    = ex;
    }
    if (b == SCANB - 1 && t == 1023) g_rowptr[NN] = base + sm[t];
}

__global__ void scatter_kernel(const int* __restrict__ src, const int* __restrict__ dst) {
    for (int e = blockIdx.x * blockDim.x + threadIdx.x; e < EE; e += gridDim.x * blockDim.x) {
        int pos = atomicAdd(&g_cur[dst[e]], 1);
        g_srcs[pos] = src[e];
    }
}

// ---------------- attention: one warp per dst node, online softmax,
// 1-deep software prefetch of next edge's k/v rows ----------------
__global__ void attn_kernel(const float* __restrict__ q, const float* __restrict__ k,
                            const float* __restrict__ v, float* __restrict__ sp)
{
    int warp = (blockIdx.x * blockDim.x + threadIdx.x) >> 5;
    int lane = threadIdx.x & 31;
    if (warp >= NN) return;
    int beg = g_rowptr[warp];
    int end = g_rowptr[warp + 1];

    float4 qv = *(const float4*)(q + (size_t)warp * DD + lane * 4);

    float m = -1e30f, den = 0.f;
    float4 acc = make_float4(0.f, 0.f, 0.f, 0.f);

    if (beg < end) {
        int s0 = g_srcs[beg];
        float4 kv = *(const float4*)(k + (size_t)s0 * DD + lane * 4);
        float4 vv = *(const float4*)(v + (size_t)s0 * DD + lane * 4);

        for (int i = beg; i < end; i++) {
            float4 kc = kv, vc = vv;
            if (i + 1 < end) {
                int s = g_srcs[i + 1];
                kv = *(const float4*)(k + (size_t)s * DD + lane * 4);
                vv = *(const float4*)(v + (size_t)s * DD + lane * 4);
            }

            float d = qv.x * kc.x + qv.y * kc.y + qv.z * kc.z + qv.w * kc.w;
            #pragma unroll
            for (int o = 16; o; o >>= 1) d += __shfl_xor_sync(0xffffffffu, d, o);
            d *= 0.08838834764831845f;

            float mnew = fmaxf(m, d);
            float r = __expf(m - mnew);
            float p = __expf(d - mnew);
            den = den * r + p;
            acc.x = acc.x * r + p * vc.x;
            acc.y = acc.y * r + p * vc.y;
            acc.z = acc.z * r + p * vc.z;
            acc.w = acc.w * r + p * vc.w;
            m = mnew;
        }
    }

    float inv = (end > beg) ? (1.f / den) : 0.f;
    float* spp = sp + (size_t)warp * DD + lane * 4;
    float4 spv = *(const float4*)spp;
    float4 o;
    o.x = acc.x * inv + spv.x;
    o.y = acc.y * inv + spv.y;
    o.z = acc.z * inv + spv.z;
    o.w = acc.w * inv + spv.w;
    *(float4*)spp = o;
}

// ---------------- tf32 tensor-core GEMM: cp.async pipelined, 2 CTAs/SM ----------
struct P4 {
    const float* W[4];
    const float* B[4];
    float*       C[4];
};

__device__ __forceinline__ float tf32r(float x) {
    unsigned u;
    asm("cvt.rna.tf32.f32 %0, %1;" : "=r"(u) : "f"(x));
    return __uint_as_float(u);
}

__device__ __forceinline__ void mma8(float* c, const unsigned* a, const unsigned* b) {
    asm volatile(
        "mma.sync.aligned.m16n8k8.row.col.f32.tf32.tf32.f32 "
        "{%0,%1,%2,%3}, {%4,%5,%6,%7}, {%8,%9}, {%0,%1,%2,%3};\n"
        : "+f"(c[0]), "+f"(c[1]), "+f"(c[2]), "+f"(c[3])
        : "r"(a[0]), "r"(a[1]), "r"(a[2]), "r"(a[3]), "r"(b[0]), "r"(b[1]));
}

template<int KC, int ZMODE, int BNB, int BNADD>
__global__ void __launch_bounds__(256, 2)
gemm_tc(const float* __restrict__ A, P4 p, const float* __restrict__ add,
        int M, int ldW, int relu)
{
    constexpr int K   = KC * 64;
    constexpr int NCH = KC * 2;
    extern __shared__ float sms[];
    float* Bs     = sms;
    float* bias_s = sms + K * 128 + 8192;
    unsigned abBase[2];
    abBase[0] = (unsigned)__cvta_generic_to_shared(sms + K * 128);
    abBase[1] = abBase[0] + 16384;

    const int tid  = threadIdx.x;
    const int lane = tid & 31;
    const int warp = tid >> 5;
    const int wm = warp & 1;
    const int wn = warp >> 1;

    int z, m0, mstep, colOff;
    if (ZMODE == 1)      { z = blockIdx.x & 3; colOff = 0;                      m0 = blockIdx.x >> 2; mstep = gridDim.x >> 2; }
    else if (ZMODE == 2) { z = 0;              colOff = (blockIdx.x & 1) * 128; m0 = blockIdx.x >> 1; mstep = gridDim.x >> 1; }
    else                 { z = 0;              colOff = 0;                      m0 = blockIdx.x;      mstep = gridDim.x; }

    const float* W    = p.W[ZMODE == 1 ? z : 0];
    const float* bias = p.B[ZMODE == 1 ? z : 0] + colOff;
    float*       C    = p.C[ZMODE == 1 ? z : 0];
    const int ldC = ldW;

    int mi_p = m0, kc_p = 0;
    int mi_c = m0, kc_c = 0;
    auto issueA = [&](int mi, int kc, int bi) {
        int rowBase = mi * 128;
        #pragma unroll
        for (int it = 0; it < 4; it++) {
            int idx = it * 256 + tid;
            int row = idx >> 3;
            int c   = idx & 7;
            int grow = rowBase + row;
            const float* src = A + (size_t)grow * K + kc * 32 + c * 4;
            unsigned dst = abBase[bi] + (row << 7) + ((c ^ (row & 7)) << 4);
            int sz = (grow < M) ? 16 : 0;
            asm volatile("cp.async.cg.shared.global [%0], [%1], 16, %2;"
                         :: "r"(dst), "l"(src), "r"(sz));
        }
    };
    auto adv = [](int& mi, int& kc, int step) {
        if (++kc == NCH) { kc = 0; mi += step; }
    };

    issueA(mi_p, kc_p, 0);
    adv(mi_p, kc_p, mstep);
    asm volatile("cp.async.commit_group;");

    #pragma unroll 4
    for (int it = 0; it < K / 8; it++) {
        int k  = it * 8 + (tid >> 5);
        int n0 = (tid & 31) * 4;
        float4 w = *(const float4*)(W + (size_t)k * ldW + colOff + n0);
        float s = BNB ? g_scale[k] : 1.f;
        float4 r;
        r.x = tf32r(w.x * s); r.y = tf32r(w.y * s);
        r.z = tf32r(w.z * s); r.w = tf32r(w.w * s);
        int kq = k >> 2, k3 = k & 3;
        int base = kq * 512 + k3 * 128 + (n0 & ~31) + ((n0 + 8 * k3) & 31);
        *(float4*)(Bs + base) = r;
    }
    if (tid < 128) {
        float b = bias[tid];
        if (BNB) {
            float a = 0.f;
            #pragma unroll 8
            for (int k = 0; k < K; k++)
                a += g_shift[k] * W[(size_t)k * ldW + colOff + tid];
            b += a;
        }
        bias_s[tid] = b;
    }
    __syncthreads();

    const int rl   = (lane & 7) + ((lane >> 3) & 1) * 8;
    const int cbit = lane >> 4;
    int innerj[4];
    #pragma unroll
    for (int j = 0; j < 4; j++)
        innerj[j] = ((j << 3) + (lane >> 2) + ((lane & 3) << 3)) & 31;

    float acc[4][4][4];
    int buf = 0;

    while (mi_c < MTILES) {
        if (mi_p < MTILES) {
            issueA(mi_p, kc_p, buf ^ 1);
            adv(mi_p, kc_p, mstep);
        }
        asm volatile("cp.async.commit_group;");
        asm volatile("cp.async.wait_group 1;");
        __syncthreads();

        if (kc_c == 0) {
            #pragma unroll
            for (int i = 0; i < 4; i++)
                #pragma unroll
                for (int j = 0; j < 4; j++)
                    #pragma unroll
                    for (int r = 0; r < 4; r++) acc[i][j][r] = 0.f;
        }

        const unsigned ab = abBase[buf];
        #pragma unroll
        for (int kt = 0; kt < 4; kt++) {
            unsigned af[4][4], bf[4][2];
            #pragma unroll
            for (int i = 0; i < 4; i++) {
                int mt = wm * 4 + i;
                unsigned addr = ab + ((mt * 16 + rl) << 7)
                              + ((((kt << 1) + cbit) ^ (lane & 7)) << 4);
                asm volatile("ldmatrix.sync.aligned.m8n8.x4.shared.b16 {%0,%1,%2,%3}, [%4];"
                             : "=r"(af[i][0]), "=r"(af[i][1]), "=r"(af[i][2]), "=r"(af[i][3])
                             : "r"(addr));
                #pragma unroll
                for (int q = 0; q < 4; q++)
                    asm("cvt.rna.tf32.f32 %0, %0;" : "+r"(af[i][q]));
            }
            int kq0 = (kc_c * 8 + kt * 2) * 512 + (lane & 3) * 128 + wn * 32;
            #pragma unroll
            for (int j = 0; j < 4; j++) {
                bf[j][0] = __float_as_uint(Bs[kq0 + innerj[j]]);
                bf[j][1] = __float_as_uint(Bs[kq0 + 512 + innerj[j]]);
            }
            #pragma unroll
            for (int i = 0; i < 4; i++)
                #pragma unroll
                for (int j = 0; j < 4; j++)
                    mma8(acc[i][j], af[i], bf[j]);
        }

        if (kc_c == NCH - 1) {
            int rowBase = mi_c * 128;
            #pragma unroll
            for (int i = 0; i < 4; i++) {
                int r0 = rowBase + wm * 64 + i * 16 + (lane >> 2);
                #pragma unroll
                for (int j = 0; j < 4; j++) {
                    int cl = wn * 32 + j * 8 + (lane & 3) * 2;
                    int cg = colOff + cl;
                    float2 bb = *(const float2*)&bias_s[cl];
                    #pragma unroll
                    for (int hh = 0; hh < 2; hh++) {
                        int r = r0 + hh * 8;
                        if (r >= M) continue;
                        float2 o;
                        o.x = acc[i][j][hh * 2 + 0] + bb.x;
                        o.y = acc[i][j][hh * 2 + 1] + bb.y;
                        if (add) {
                            float2 ad = *(const float2*)(add + (size_t)r * ldC + cg);
                            if (BNADD) {
                                ad.x = ad.x * g_scale[cg]     + g_shift[cg];
                                ad.y = ad.y * g_scale[cg + 1] + g_shift[cg + 1];
                            }
                            o.x += ad.x; o.y += ad.y;
                        }
                        if (relu) { o.x = fmaxf(o.x, 0.f); o.y = fmaxf(o.y, 0.f); }
                        *(float2*)(C + (size_t)r * ldC + cg) = o;
                    }
                }
            }
        }
        __syncthreads();
        buf ^= 1;
        adv(mi_c, kc_c, mstep);
    }
}

// ---------------- BatchNorm: stats + last-block finalize (R11 proven) ----------
__global__ void bnstats_kernel(const float* __restrict__ h,
                               const float* __restrict__ g, const float* __restrict__ be,
                               int which) {
    int c = threadIdx.x;
    float s = 0.f, s2 = 0.f;
    for (int r = blockIdx.x; r < NN; r += gridDim.x) {
        float vv = h[(size_t)r * DD + c];
        s += vv;
        s2 += vv * vv;
    }
    atomicAdd(&g_sums[which * 2 * DD + c], s);
    atomicAdd(&g_sums[which * 2 * DD + DD + c], s2);

    __shared__ bool last;
    __threadfence();
    if (threadIdx.x == 0) {
        int t = atomicAdd(&g_bnctr[which], 1);
        last = (t == (int)gridDim.x - 1);
    }
    __syncthreads();
    if (last) {
        float mu  = g_sums[which * 2 * DD + c] / (float)NN;
        float var = g_sums[which * 2 * DD + DD + c] / (float)NN - mu * mu;
        float sc = g[c] * rsqrtf(var + EPSV);
        g_scale[which * DD + c] = sc;
        g_shift[which * DD + c] = be[c] - mu * sc;
        if (threadIdx.x == 0) g_bnctr[which] = 0;
    }
}

__global__ void bnapply_kernel(float* __restrict__ h, int which) {
    const int total = NN * DD / 4;
    for (int i = blockIdx.x * blockDim.x + threadIdx.x; i < total; i += gridDim.x * blockDim.x) {
        float4 vv = ((float4*)h)[i];
        int cb = (i & 31) << 2;
        float4 sc = *(const float4*)&g_scale[which * DD + cb];
        float4 sh = *(const float4*)&g_shift[which * DD + cb];
        vv.x = vv.x * sc.x + sh.x;
        vv.y = vv.y * sc.y + sh.y;
        vv.z = vv.z * sc.z + sh.z;
        vv.w = vv.w * sc.w + sh.w;
        ((float4*)h)[i] = vv;
    }
}

// ---------------- launch ----------------
extern "C" void kernel_launch(void* const* d_in, const int* in_sizes, int n_in,
                              void* d_out, int out_size)
{
    const float* x  = (const float*)d_in[0];
    const int*   ei = (const int*)  d_in[1];
    const float *Wq = (const float*)d_in[2],  *bq = (const float*)d_in[3];
    const float *Wk = (const float*)d_in[4],  *bk = (const float*)d_in[5];
    const float *Wv = (const float*)d_in[6],  *bv = (const float*)d_in[7];
    const float *Ws = (const float*)d_in[8],  *bs = (const float*)d_in[9];
    const float *WO = (const float*)d_in[10], *bO = (const float*)d_in[11];
    const float *W1 = (const float*)d_in[12], *b1 = (const float*)d_in[13];
    const float *W2 = (const float*)d_in[14], *b2 = (const float*)d_in[15];
    const float *g1 = (const float*)d_in[16], *be1 = (const float*)d_in[17];
    const float *g2 = (const float*)d_in[18], *be2 = (const float*)d_in[19];
    float* out = (float*)d_out;

    const int* src = ei;
    const int* dst = ei + EE;

    float *q, *k, *v, *sp, *h, *t;
    cudaGetSymbolAddress((void**)&q,  g_q);
    cudaGetSymbolAddress((void**)&k,  g_k);
    cudaGetSymbolAddress((void**)&v,  g_v);
    cudaGetSymbolAddress((void**)&sp, g_sp);
    cudaGetSymbolAddress((void**)&h,  g_h);
    cudaGetSymbolAddress((void**)&t,  g_t);

    const int SM2 = 2 * 64 * 128 * 4 + 32768 + 512;   // KC=2: 2 CTAs/SM
    const int SM4 = 4 * 64 * 128 * 4 + 32768 + 512;   // KC=4: 1 CTA/SM
    cudaFuncSetAttribute(gemm_tc<2,1,0,0>, cudaFuncAttributeMaxDynamicSharedMemorySize, SM2);
    cudaFuncSetAttribute(gemm_tc<2,0,0,0>, cudaFuncAttributeMaxDynamicSharedMemorySize, SM2);
    cudaFuncSetAttribute(gemm_tc<2,2,1,0>, cudaFuncAttributeMaxDynamicSharedMemorySize, SM2);
    cudaFuncSetAttribute(gemm_tc<4,0,0,1>, cudaFuncAttributeMaxDynamicSharedMemorySize, SM4);

    cudaStream_t s1;
    cudaEvent_t ev0, ev1;
    cudaStreamCreateWithFlags(&s1, cudaStreamNonBlocking);
    cudaEventCreateWithFlags(&ev0, cudaEventDisableTiming);
    cudaEventCreateWithFlags(&ev1, cudaEventDisableTiming);

    // ---- fork: CSR build on s1, QKVS GEMM on main, overlapped.
    cudaEventRecord(ev0, 0);
    cudaStreamWaitEvent(s1, ev0, 0);
    zero_kernel<<<(NN + 255) / 256, 256, 0, s1>>>();   // launch 1
    hist_kernel<<<512, 256, 0, s1>>>(dst);             // launch 2
    scanA_kernel<<<SCANB, 1024, 0, s1>>>();            // launch 3

    // fused Q/K/V/S projections (main stream) — launch 4 (profiled)
    {
        P4 p;
        p.W[0] = Wq; p.B[0] = bq; p.C[0] = q;
        p.W[1] = Wk; p.B[1] = bk; p.C[1] = k;
        p.W[2] = Wv; p.B[2] = bv; p.C[2] = v;
        p.W[3] = Ws; p.B[3] = bs; p.C[3] = sp;
        gemm_tc<2,1,0,0><<<296, 256, SM2>>>(x, p, nullptr, NN, 128, 0);
    }

    scanB_kernel<<<SCANB, 1024, 0, s1>>>();            // launch 5
    scatter_kernel<<<512, 256, 0, s1>>>(src, dst);     // launch 6
    cudaEventRecord(ev1, s1);

    // ---- join ----
    cudaStreamWaitEvent(0, ev1, 0);

    // attention (1-deep prefetch; writes agg + sp into sp)
    attn_kernel<<<(NN * 32 + 255) / 256, 256>>>(q, k, v, sp);

    // h = sp @ WO + bO + x
    {
        P4 p = {};
        p.W[0] = WO; p.B[0] = bO; p.C[0] = h;
        gemm_tc<2,0,0,0><<<296, 256, SM2>>>(sp, p, x, NN, 128, 0);
    }

    // BN1 stats + finalize (apply folded into FFN1 / FFN2)
    bnstats_kernel<<<256, 128>>>(h, g1, be1, 0);

    // FFN1: t = relu(BN1(h) @ W1 + b1)
    {
        P4 p = {};
        p.W[0] = W1; p.B[0] = b1; p.C[0] = t;
        gemm_tc<2,2,1,0><<<296, 256, SM2>>>(h, p, nullptr, NN, 256, 1);
    }
    // FFN2: out = t @ W2 + b2 + BN1(h)
    {
        P4 p = {};
        p.W[0] = W2; p.B[0] = b2; p.C[0] = out;
        gemm_tc<4,0,0,1><<<148, 256, SM4>>>(t, p, h, NN, 128, 0);
    }

    // BN2 stats + finalize, then apply
    bnstats_kernel<<<256, 128>>>(out, g2, be2, 1);
    bnapply_kernel<<<512, 256>>>(out, 1);
}

// round 15
// speedup vs baseline: 1.2911x; 1.2500x over previous
#include <cuda_runtime.h>

#define NN 50000
#define DD 128
#define EE 800000
#define EPSV 1e-5f
#define MTILES 391  // ceil(50000/128)
#define SCANB 49    // ceil(50000/1024)

// ---------------- scratch ----------------
__device__ __align__(16) float g_q [NN*DD];
__device__ __align__(16) float g_k [NN*DD];
__device__ __align__(16) float g_v [NN*DD];
__device__ __align__(16) float g_sp[NN*DD];
__device__ __align__(16) float g_h [NN*DD];
__device__ __align__(16) float g_t [NN*2*DD];
__device__ int   g_cnt[NN];
__device__ int   g_rowptr[NN+1];
__device__ int   g_cur[NN];
__device__ int   g_srcs[EE];
__device__ int   g_part[SCANB];
__device__ __align__(16) float g_sums [4*DD];
__device__ __align__(16) float g_scale[2*DD];
__device__ __align__(16) float g_shift[2*DD];

// ---------------- CSR build (R11 proven) ----------------
__global__ void zero_kernel() {
    int i = blockIdx.x * blockDim.x + threadIdx.x;
    if (i < NN) g_cnt[i] = 0;
    if (i < 4*DD) g_sums[i] = 0.f;
}

__global__ void hist_kernel(const int* __restrict__ dst) {
    for (int e = blockIdx.x * blockDim.x + threadIdx.x; e < EE; e += gridDim.x * blockDim.x)
        atomicAdd(&g_cnt[dst[e]], 1);
}

__global__ void scanA_kernel() {
    __shared__ int sm[1024];
    int idx = blockIdx.x * 1024 + threadIdx.x;
    sm[threadIdx.x] = (idx < NN) ? g_cnt[idx] : 0;
    __syncthreads();
    #pragma unroll
    for (int off = 512; off; off >>= 1) {
        if (threadIdx.x < off) sm[threadIdx.x] += sm[threadIdx.x + off];
        __syncthreads();
    }
    if (threadIdx.x == 0) g_part[blockIdx.x] = sm[0];
}

__global__ void scanB_kernel() {
    __shared__ int sm[1024];
    int b = blockIdx.x, t = threadIdx.x;
    int idx = b * 1024 + t;
    int c = (idx < NN) ? g_cnt[idx] : 0;
    sm[t] = c;
    __syncthreads();
    for (int off = 1; off < 1024; off <<= 1) {
        int v = (t >= off) ? sm[t - off] : 0;
        __syncthreads();
        sm[t] += v;
        __syncthreads();
    }
    int base = 0;
    for (int j = 0; j < b; j++) base += g_part[j];
    if (idx < NN) {
        int ex = base + sm[t] - c;
        g_rowptr[idx] = ex;
        g_cur[idx]    = ex;
    }
    if (b == SCANB - 1 && t == 1023) g_rowptr[NN] = base + sm[t];
}

__global__ void scatter_kernel(const int* __restrict__ src, const int* __restrict__ dst) {
    for (int e = blockIdx.x * blockDim.x + threadIdx.x; e < EE; e += gridDim.x * blockDim.x) {
        int pos = atomicAdd(&g_cur[dst[e]], 1);
        g_srcs[pos] = src[e];
    }
}

// ---------------- attention (R14: 1-deep prefetch) ----------------
__global__ void attn_kernel(const float* __restrict__ q, const float* __restrict__ k,
                            const float* __restrict__ v, float* __restrict__ sp)
{
    int warp = (blockIdx.x * blockDim.x + threadIdx.x) >> 5;
    int lane = threadIdx.x & 31;
    if (warp >= NN) return;
    int beg = g_rowptr[warp];
    int end = g_rowptr[warp + 1];

    float4 qv = *(const float4*)(q + (size_t)warp * DD + lane * 4);

    float m = -1e30f, den = 0.f;
    float4 acc = make_float4(0.f, 0.f, 0.f, 0.f);

    if (beg < end) {
        int s0 = g_srcs[beg];
        float4 kv = *(const float4*)(k + (size_t)s0 * DD + lane * 4);
        float4 vv = *(const float4*)(v + (size_t)s0 * DD + lane * 4);

        for (int i = beg; i < end; i++) {
            float4 kc = kv, vc = vv;
            if (i + 1 < end) {
                int s = g_srcs[i + 1];
                kv = *(const float4*)(k + (size_t)s * DD + lane * 4);
                vv = *(const float4*)(v + (size_t)s * DD + lane * 4);
            }

            float d = qv.x * kc.x + qv.y * kc.y + qv.z * kc.z + qv.w * kc.w;
            #pragma unroll
            for (int o = 16; o; o >>= 1) d += __shfl_xor_sync(0xffffffffu, d, o);
            d *= 0.08838834764831845f;

            float mnew = fmaxf(m, d);
            float r = __expf(m - mnew);
            float p = __expf(d - mnew);
            den = den * r + p;
            acc.x = acc.x * r + p * vc.x;
            acc.y = acc.y * r + p * vc.y;
            acc.z = acc.z * r + p * vc.z;
            acc.w = acc.w * r + p * vc.w;
            m = mnew;
        }
    }

    float inv = (end > beg) ? (1.f / den) : 0.f;
    float* spp = sp + (size_t)warp * DD + lane * 4;
    float4 spv = *(const float4*)spp;
    float4 o;
    o.x = acc.x * inv + spv.x;
    o.y = acc.y * inv + spv.y;
    o.z = acc.z * inv + spv.z;
    o.w = acc.w * inv + spv.w;
    *(float4*)spp = o;
}

// ---------------- tf32 tensor-core GEMM: cp.async, 2 CTAs/SM, fused BN stats ----
struct P4 {
    const float* W[4];
    const float* B[4];
    float*       C[4];
};

__device__ __forceinline__ float tf32r(float x) {
    unsigned u;
    asm("cvt.rna.tf32.f32 %0, %1;" : "=r"(u) : "f"(x));
    return __uint_as_float(u);
}

__device__ __forceinline__ void mma8(float* c, const unsigned* a, const unsigned* b) {
    asm volatile(
        "mma.sync.aligned.m16n8k8.row.col.f32.tf32.tf32.f32 "
        "{%0,%1,%2,%3}, {%4,%5,%6,%7}, {%8,%9}, {%0,%1,%2,%3};\n"
        : "+f"(c[0]), "+f"(c[1]), "+f"(c[2]), "+f"(c[3])
        : "r"(a[0]), "r"(a[1]), "r"(a[2]), "r"(a[3]), "r"(b[0]), "r"(b[1]));
}

// BNST: -1 = no stats; 0/1 = accumulate column sum/sumsq of C into g_sums[BNST].
template<int KC, int ZMODE, int BNB, int BNADD, int BNST>
__global__ void __launch_bounds__(256, 2)
gemm_tc(const float* __restrict__ A, P4 p, const float* __restrict__ add,
        int M, int ldW, int relu)
{
    constexpr int K   = KC * 64;
    constexpr int NCH = KC * 2;
    extern __shared__ float sms[];
    float* Bs     = sms;
    float* bias_s = sms + K * 128 + 8192;
    unsigned abBase[2];
    abBase[0] = (unsigned)__cvta_generic_to_shared(sms + K * 128);
    abBase[1] = abBase[0] + 16384;

    const int tid  = threadIdx.x;
    const int lane = tid & 31;
    const int warp = tid >> 5;
    const int wm = warp & 1;
    const int wn = warp >> 1;

    int z, m0, mstep, colOff;
    if (ZMODE == 1)      { z = blockIdx.x & 3; colOff = 0;                      m0 = blockIdx.x >> 2; mstep = gridDim.x >> 2; }
    else if (ZMODE == 2) { z = 0;              colOff = (blockIdx.x & 1) * 128; m0 = blockIdx.x >> 1; mstep = gridDim.x >> 1; }
    else                 { z = 0;              colOff = 0;                      m0 = blockIdx.x;      mstep = gridDim.x; }

    const float* W    = p.W[ZMODE == 1 ? z : 0];
    const float* bias = p.B[ZMODE == 1 ? z : 0] + colOff;
    float*       C    = p.C[ZMODE == 1 ? z : 0];
    const int ldC = ldW;

    int mi_p = m0, kc_p = 0;
    int mi_c = m0, kc_c = 0;
    auto issueA = [&](int mi, int kc, int bi) {
        int rowBase = mi * 128;
        #pragma unroll
        for (int it = 0; it < 4; it++) {
            int idx = it * 256 + tid;
            int row = idx >> 3;
            int c   = idx & 7;
            int grow = rowBase + row;
            const float* src = A + (size_t)grow * K + kc * 32 + c * 4;
            unsigned dst = abBase[bi] + (row << 7) + ((c ^ (row & 7)) << 4);
            int sz = (grow < M) ? 16 : 0;
            asm volatile("cp.async.cg.shared.global [%0], [%1], 16, %2;"
                         :: "r"(dst), "l"(src), "r"(sz));
        }
    };
    auto adv = [](int& mi, int& kc, int step) {
        if (++kc == NCH) { kc = 0; mi += step; }
    };

    issueA(mi_p, kc_p, 0);
    adv(mi_p, kc_p, mstep);
    asm volatile("cp.async.commit_group;");

    #pragma unroll 4
    for (int it = 0; it < K / 8; it++) {
        int k  = it * 8 + (tid >> 5);
        int n0 = (tid & 31) * 4;
        float4 w = *(const float4*)(W + (size_t)k * ldW + colOff + n0);
        float s = BNB ? g_scale[k] : 1.f;
        float4 r;
        r.x = tf32r(w.x * s); r.y = tf32r(w.y * s);
        r.z = tf32r(w.z * s); r.w = tf32r(w.w * s);
        int kq = k >> 2, k3 = k & 3;
        int base = kq * 512 + k3 * 128 + (n0 & ~31) + ((n0 + 8 * k3) & 31);
        *(float4*)(Bs + base) = r;
    }
    if (tid < 128) {
        float b = bias[tid];
        if (BNB) {
            float a = 0.f;
            #pragma unroll 8
            for (int k = 0; k < K; k++)
                a += g_shift[k] * W[(size_t)k * ldW + colOff + tid];
            b += a;
        }
        bias_s[tid] = b;
    }
    __syncthreads();

    const int rl   = (lane & 7) + ((lane >> 3) & 1) * 8;
    const int cbit = lane >> 4;
    int innerj[4];
    #pragma unroll
    for (int j = 0; j < 4; j++)
        innerj[j] = ((j << 3) + (lane >> 2) + ((lane & 3) << 3)) & 31;

    float acc[4][4][4];
    int buf = 0;

    while (mi_c < MTILES) {
        if (mi_p < MTILES) {
            issueA(mi_p, kc_p, buf ^ 1);
            adv(mi_p, kc_p, mstep);
        }
        asm volatile("cp.async.commit_group;");
        asm volatile("cp.async.wait_group 1;");
        __syncthreads();

        if (kc_c == 0) {
            #pragma unroll
            for (int i = 0; i < 4; i++)
                #pragma unroll
                for (int j = 0; j < 4; j++)
                    #pragma unroll
                    for (int r = 0; r < 4; r++) acc[i][j][r] = 0.f;
        }

        const unsigned ab = abBase[buf];
        #pragma unroll
        for (int kt = 0; kt < 4; kt++) {
            unsigned af[4][4], bf[4][2];
            #pragma unroll
            for (int i = 0; i < 4; i++) {
                int mt = wm * 4 + i;
                unsigned addr = ab + ((mt * 16 + rl) << 7)
                              + ((((kt << 1) + cbit) ^ (lane & 7)) << 4);
                asm volatile("ldmatrix.sync.aligned.m8n8.x4.shared.b16 {%0,%1,%2,%3}, [%4];"
                             : "=r"(af[i][0]), "=r"(af[i][1]), "=r"(af[i][2]), "=r"(af[i][3])
                             : "r"(addr));
                #pragma unroll
                for (int q = 0; q < 4; q++)
                    asm("cvt.rna.tf32.f32 %0, %0;" : "+r"(af[i][q]));
            }
            int kq0 = (kc_c * 8 + kt * 2) * 512 + (lane & 3) * 128 + wn * 32;
            #pragma unroll
            for (int j = 0; j < 4; j++) {
                bf[j][0] = __float_as_uint(Bs[kq0 + innerj[j]]);
                bf[j][1] = __float_as_uint(Bs[kq0 + 512 + innerj[j]]);
            }
            #pragma unroll
            for (int i = 0; i < 4; i++)
                #pragma unroll
                for (int j = 0; j < 4; j++)
                    mma8(acc[i][j], af[i], bf[j]);
        }

        if (kc_c == NCH - 1) {
            int rowBase = mi_c * 128;
            #pragma unroll
            for (int j = 0; j < 4; j++) {
                int cl = wn * 32 + j * 8 + (lane & 3) * 2;
                int cg = colOff + cl;
                float2 bb = *(const float2*)&bias_s[cl];
                float sx = 0.f, qx = 0.f, sy = 0.f, qy = 0.f;
                #pragma unroll
                for (int i = 0; i < 4; i++) {
                    int r0 = rowBase + wm * 64 + i * 16 + (lane >> 2);
                    #pragma unroll
                    for (int hh = 0; hh < 2; hh++) {
                        int r = r0 + hh * 8;
                        if (r >= M) continue;
                        float2 o;
                        o.x = acc[i][j][hh * 2 + 0] + bb.x;
                        o.y = acc[i][j][hh * 2 + 1] + bb.y;
                        if (add) {
                            float2 ad = *(const float2*)(add + (size_t)r * ldC + cg);
                            if (BNADD) {
                                ad.x = ad.x * g_scale[cg]     + g_shift[cg];
                                ad.y = ad.y * g_scale[cg + 1] + g_shift[cg + 1];
                            }
                            o.x += ad.x; o.y += ad.y;
                        }
                        if (relu) { o.x = fmaxf(o.x, 0.f); o.y = fmaxf(o.y, 0.f); }
                        *(float2*)(C + (size_t)r * ldC + cg) = o;
                        if (BNST >= 0) {
                            sx += o.x; qx += o.x * o.x;
                            sy += o.y; qy += o.y * o.y;
                        }
                    }
                }
                if (BNST >= 0) {
                    #pragma unroll
                    for (int off = 16; off >= 4; off >>= 1) {
                        sx += __shfl_xor_sync(0xffffffffu, sx, off);
                        qx += __shfl_xor_sync(0xffffffffu, qx, off);
                        sy += __shfl_xor_sync(0xffffffffu, sy, off);
                        qy += __shfl_xor_sync(0xffffffffu, qy, off);
                    }
                    if ((lane >> 2) == 0) {
                        atomicAdd(&g_sums[BNST * 2 * DD + cg],          sx);
                        atomicAdd(&g_sums[BNST * 2 * DD + DD + cg],     qx);
                        atomicAdd(&g_sums[BNST * 2 * DD + cg + 1],      sy);
                        atomicAdd(&g_sums[BNST * 2 * DD + DD + cg + 1], qy);
                    }
                }
            }
        }
        __syncthreads();
        buf ^= 1;
        adv(mi_c, kc_c, mstep);
    }
}

// ---------------- BN finalize (1 block, 128 threads) ----------------
__global__ void bnfin_kernel(const float* __restrict__ g, const float* __restrict__ be,
                             int which) {
    int c = threadIdx.x;
    float mu  = g_sums[which * 2 * DD + c] / (float)NN;
    float var = g_sums[which * 2 * DD + DD + c] / (float)NN - mu * mu;
    float sc = g[c] * rsqrtf(var + EPSV);
    g_scale[which * DD + c] = sc;
    g_shift[which * DD + c] = be[c] - mu * sc;
}

__global__ void bnapply_kernel(float* __restrict__ h, int which) {
    const int total = NN * DD / 4;
    for (int i = blockIdx.x * blockDim.x + threadIdx.x; i < total; i += gridDim.x * blockDim.x) {
        float4 vv = ((float4*)h)[i];
        int cb = (i & 31) << 2;
        float4 sc = *(const float4*)&g_scale[which * DD + cb];
        float4 sh = *(const float4*)&g_shift[which * DD + cb];
        vv.x = vv.x * sc.x + sh.x;
        vv.y = vv.y * sc.y + sh.y;
        vv.z = vv.z * sc.z + sh.z;
        vv.w = vv.w * sc.w + sh.w;
        ((float4*)h)[i] = vv;
    }
}

// ---------------- launch ----------------
extern "C" void kernel_launch(void* const* d_in, const int* in_sizes, int n_in,
                              void* d_out, int out_size)
{
    const float* x  = (const float*)d_in[0];
    const int*   ei = (const int*)  d_in[1];
    const float *Wq = (const float*)d_in[2],  *bq = (const float*)d_in[3];
    const float *Wk = (const float*)d_in[4],  *bk = (const float*)d_in[5];
    const float *Wv = (const float*)d_in[6],  *bv = (const float*)d_in[7];
    const float *Ws = (const float*)d_in[8],  *bs = (const float*)d_in[9];
    const float *WO = (const float*)d_in[10], *bO = (const float*)d_in[11];
    const float *W1 = (const float*)d_in[12], *b1 = (const float*)d_in[13];
    const float *W2 = (const float*)d_in[14], *b2 = (const float*)d_in[15];
    const float *g1 = (const float*)d_in[16], *be1 = (const float*)d_in[17];
    const float *g2 = (const float*)d_in[18], *be2 = (const float*)d_in[19];
    float* out = (float*)d_out;

    const int* src = ei;
    const int* dst = ei + EE;

    float *q, *k, *v, *sp, *h, *t;
    cudaGetSymbolAddress((void**)&q,  g_q);
    cudaGetSymbolAddress((void**)&k,  g_k);
    cudaGetSymbolAddress((void**)&v,  g_v);
    cudaGetSymbolAddress((void**)&sp, g_sp);
    cudaGetSymbolAddress((void**)&h,  g_h);
    cudaGetSymbolAddress((void**)&t,  g_t);

    const int SM2 = 2 * 64 * 128 * 4 + 32768 + 512;   // KC=2: 2 CTAs/SM
    const int SM4 = 4 * 64 * 128 * 4 + 32768 + 512;   // KC=4: 1 CTA/SM
    cudaFuncSetAttribute(gemm_tc<2,1,0,0,-1>, cudaFuncAttributeMaxDynamicSharedMemorySize, SM2);
    cudaFuncSetAttribute(gemm_tc<2,0,0,0,0>,  cudaFuncAttributeMaxDynamicSharedMemorySize, SM2);
    cudaFuncSetAttribute(gemm_tc<2,2,1,0,-1>, cudaFuncAttributeMaxDynamicSharedMemorySize, SM2);
    cudaFuncSetAttribute(gemm_tc<4,0,0,1,1>,  cudaFuncAttributeMaxDynamicSharedMemorySize, SM4);

    cudaStream_t s1;
    cudaEvent_t ev0, ev1;
    cudaStreamCreateWithFlags(&s1, cudaStreamNonBlocking);
    cudaEventCreateWithFlags(&ev0, cudaEventDisableTiming);
    cudaEventCreateWithFlags(&ev1, cudaEventDisableTiming);

    // ---- fork: CSR build (+ g_sums zeroing) on s1, QKVS GEMM on main.
    cudaEventRecord(ev0, 0);
    cudaStreamWaitEvent(s1, ev0, 0);
    zero_kernel<<<(NN + 255) / 256, 256, 0, s1>>>();   // launch 1
    hist_kernel<<<512, 256, 0, s1>>>(dst);             // launch 2
    scanA_kernel<<<SCANB, 1024, 0, s1>>>();            // launch 3

    // fused Q/K/V/S projections (main stream) — launch 4 (profiled)
    {
        P4 p;
        p.W[0] = Wq; p.B[0] = bq; p.C[0] = q;
        p.W[1] = Wk; p.B[1] = bk; p.C[1] = k;
        p.W[2] = Wv; p.B[2] = bv; p.C[2] = v;
        p.W[3] = Ws; p.B[3] = bs; p.C[3] = sp;
        gemm_tc<2,1,0,0,-1><<<296, 256, SM2>>>(x, p, nullptr, NN, 128, 0);
    }

    scanB_kernel<<<SCANB, 1024, 0, s1>>>();            // launch 5
    scatter_kernel<<<512, 256, 0, s1>>>(src, dst);     // launch 6
    cudaEventRecord(ev1, s1);

    // ---- join ----
    cudaStreamWaitEvent(0, ev1, 0);

    // attention (writes agg + sp into sp)
    attn_kernel<<<(NN * 32 + 255) / 256, 256>>>(q, k, v, sp);

    // h = sp @ WO + bO + x, with fused BN1 stats accumulation
    {
        P4 p = {};
        p.W[0] = WO; p.B[0] = bO; p.C[0] = h;
        gemm_tc<2,0,0,0,0><<<296, 256, SM2>>>(sp, p, x, NN, 128, 0);
    }
    bnfin_kernel<<<1, 128>>>(g1, be1, 0);

    // FFN1: t = relu(BN1(h) @ W1 + b1)
    {
        P4 p = {};
        p.W[0] = W1; p.B[0] = b1; p.C[0] = t;
        gemm_tc<2,2,1,0,-1><<<296, 256, SM2>>>(h, p, nullptr, NN, 256, 1);
    }
    // FFN2: out = t @ W2 + b2 + BN1(h), with fused BN2 stats accumulation
    {
        P4 p = {};
        p.W[0] = W2; p.B[0] = b2; p.C[0] = out;
        gemm_tc<4,0,0,1,1><<<148, 256, SM4>>>(t, p, h, NN, 128, 0);
    }
    bnfin_kernel<<<1, 128>>>(g2, be2, 1);

    // BN2 apply
    bnapply_kernel<<<512, 256>>>(out, 1);
}

// round 16
// speedup vs baseline: 1.3319x; 1.0316x over previous
#include <cuda_runtime.h>

#define NN 50000
#define DD 128
#define EE 800000
#define EPSV 1e-5f
#define MTILES 391  // ceil(50000/128)
#define SCANB 49    // ceil(50000/1024)

// ---------------- scratch ----------------
__device__ __align__(16) float g_q [NN*DD];
__device__ __align__(16) float g_k [NN*DD];
__device__ __align__(16) float g_v [NN*DD];
__device__ __align__(16) float g_sp[NN*DD];
__device__ __align__(16) float g_h [NN*DD];
__device__ __align__(16) float g_t [NN*2*DD];
__device__ int   g_cnt[NN];
__device__ int   g_rowptr[NN+1];
__device__ int   g_cur[NN];
__device__ int   g_srcs[EE];
__device__ int   g_part[SCANB];
__device__ __align__(16) float g_sums [4*DD];

// ---------------- CSR build (R11 proven) ----------------
__global__ void zero_kernel() {
    int i = blockIdx.x * blockDim.x + threadIdx.x;
    if (i < NN) g_cnt[i] = 0;
    if (i < 4*DD) g_sums[i] = 0.f;
}

__global__ void hist_kernel(const int* __restrict__ dst) {
    for (int e = blockIdx.x * blockDim.x + threadIdx.x; e < EE; e += gridDim.x * blockDim.x)
        atomicAdd(&g_cnt[dst[e]], 1);
}

__global__ void scanA_kernel() {
    __shared__ int sm[1024];
    int idx = blockIdx.x * 1024 + threadIdx.x;
    sm[threadIdx.x] = (idx < NN) ? g_cnt[idx] : 0;
    __syncthreads();
    #pragma unroll
    for (int off = 512; off; off >>= 1) {
        if (threadIdx.x < off) sm[threadIdx.x] += sm[threadIdx.x + off];
        __syncthreads();
    }
    if (threadIdx.x == 0) g_part[blockIdx.x] = sm[0];
}

__global__ void scanB_kernel() {
    __shared__ int sm[1024];
    int b = blockIdx.x, t = threadIdx.x;
    int idx = b * 1024 + t;
    int c = (idx < NN) ? g_cnt[idx] : 0;
    sm[t] = c;
    __syncthreads();
    for (int off = 1; off < 1024; off <<= 1) {
        int v = (t >= off) ? sm[t - off] : 0;
        __syncthreads();
        sm[t] += v;
        __syncthreads();
    }
    int base = 0;
    for (int j = 0; j < b; j++) base += g_part[j];
    if (idx < NN) {
        int ex = base + sm[t] - c;
        g_rowptr[idx] = ex;
        g_cur[idx]    = ex;
    }
    if (b == SCANB - 1 && t == 1023) g_rowptr[NN] = base + sm[t];
}

__global__ void scatter_kernel(const int* __restrict__ src, const int* __restrict__ dst) {
    for (int e = blockIdx.x * blockDim.x + threadIdx.x; e < EE; e += gridDim.x * blockDim.x) {
        int pos = atomicAdd(&g_cur[dst[e]], 1);
        g_srcs[pos] = src[e];
    }
}

// ---------------- attention: one warp per dst, PAIRWISE online softmax ---------
// Two edges per state update: keeps max-shift exactness, halves the cross-edge
// rescale dependency chain, doubles natural load MLP.
__global__ void attn_kernel(const float* __restrict__ q, const float* __restrict__ k,
                            const float* __restrict__ v, float* __restrict__ sp)
{
    int warp = (blockIdx.x * blockDim.x + threadIdx.x) >> 5;
    int lane = threadIdx.x & 31;
    if (warp >= NN) return;
    int beg = g_rowptr[warp];
    int end = g_rowptr[warp + 1];

    float4 qv = *(const float4*)(q + (size_t)warp * DD + lane * 4);
    const float SC = 0.08838834764831845f;  // 1/sqrt(128)

    float m = -1e30f, den = 0.f;
    float4 acc = make_float4(0.f, 0.f, 0.f, 0.f);

    int i = beg;
    for (; i + 2 <= end; i += 2) {
        int s0 = g_srcs[i];
        int s1 = g_srcs[i + 1];
        float4 k0 = *(const float4*)(k + (size_t)s0 * DD + lane * 4);
        float4 k1 = *(const float4*)(k + (size_t)s1 * DD + lane * 4);
        float4 v0 = *(const float4*)(v + (size_t)s0 * DD + lane * 4);
        float4 v1 = *(const float4*)(v + (size_t)s1 * DD + lane * 4);

        float d0 = qv.x * k0.x + qv.y * k0.y + qv.z * k0.z + qv.w * k0.w;
        float d1 = qv.x * k1.x + qv.y * k1.y + qv.z * k1.z + qv.w * k1.w;
        #pragma unroll
        for (int o = 16; o; o >>= 1) {
            d0 += __shfl_xor_sync(0xffffffffu, d0, o);
            d1 += __shfl_xor_sync(0xffffffffu, d1, o);
        }
        d0 *= SC;
        d1 *= SC;

        float mnew = fmaxf(m, fmaxf(d0, d1));
        float r  = __expf(m - mnew);
        float p0 = __expf(d0 - mnew);
        float p1 = __expf(d1 - mnew);
        den = den * r + p0 + p1;
        acc.x = acc.x * r + p0 * v0.x + p1 * v1.x;
        acc.y = acc.y * r + p0 * v0.y + p1 * v1.y;
        acc.z = acc.z * r + p0 * v0.z + p1 * v1.z;
        acc.w = acc.w * r + p0 * v0.w + p1 * v1.w;
        m = mnew;
    }
    for (; i < end; i++) {
        int s = g_srcs[i];
        float4 kv = *(const float4*)(k + (size_t)s * DD + lane * 4);
        float4 vv = *(const float4*)(v + (size_t)s * DD + lane * 4);
        float d = qv.x * kv.x + qv.y * kv.y + qv.z * kv.z + qv.w * kv.w;
        #pragma unroll
        for (int o = 16; o; o >>= 1) d += __shfl_xor_sync(0xffffffffu, d, o);
        d *= SC;
        float mnew = fmaxf(m, d);
        float r = __expf(m - mnew);
        float p = __expf(d - mnew);
        den = den * r + p;
        acc.x = acc.x * r + p * vv.x;
        acc.y = acc.y * r + p * vv.y;
        acc.z = acc.z * r + p * vv.z;
        acc.w = acc.w * r + p * vv.w;
        m = mnew;
    }

    float inv = (end > beg) ? (1.f / den) : 0.f;
    float* spp = sp + (size_t)warp * DD + lane * 4;
    float4 spv = *(const float4*)spp;
    float4 o;
    o.x = acc.x * inv + spv.x;
    o.y = acc.y * inv + spv.y;
    o.z = acc.z * inv + spv.z;
    o.w = acc.w * inv + spv.w;
    *(float4*)spp = o;
}

// ---------------- tf32 tensor-core GEMM: cp.async, 2 CTAs/SM, fused BN ---------
struct P4 {
    const float* W[4];
    const float* B[4];
    float*       C[4];
};

__device__ __forceinline__ float tf32r(float x) {
    unsigned u;
    asm("cvt.rna.tf32.f32 %0, %1;" : "=r"(u) : "f"(x));
    return __uint_as_float(u);
}

__device__ __forceinline__ void mma8(float* c, const unsigned* a, const unsigned* b) {
    asm volatile(
        "mma.sync.aligned.m16n8k8.row.col.f32.tf32.tf32.f32 "
        "{%0,%1,%2,%3}, {%4,%5,%6,%7}, {%8,%9}, {%0,%1,%2,%3};\n"
        : "+f"(c[0]), "+f"(c[1]), "+f"(c[2]), "+f"(c[3])
        : "r"(a[0]), "r"(a[1]), "r"(a[2]), "r"(a[3]), "r"(b[0]), "r"(b[1]));
}

// BNB: fold BN1 (from g_sums[0] + bng/bnbe) into B + bias.
// BNADD: apply BN1 (from g_sums[0] + bng/bnbe) to add-path.
// BNST: -1 none; 0/1 accumulate column sum/sumsq of C into g_sums[BNST].
template<int KC, int ZMODE, int BNB, int BNADD, int BNST>
__global__ void __launch_bounds__(256, 2)
gemm_tc(const float* __restrict__ A, P4 p, const float* __restrict__ add,
        const float* __restrict__ bng, const float* __restrict__ bnbe,
        int M, int ldW, int relu)
{
    constexpr int K   = KC * 64;
    constexpr int NCH = KC * 2;
    extern __shared__ float sms[];
    float* Bs      = sms;
    float* bias_s  = sms + K * 128 + 8192;
    float* scale_s = bias_s + 128;
    float* shift_s = bias_s + 256;
    unsigned abBase[2];
    abBase[0] = (unsigned)__cvta_generic_to_shared(sms + K * 128);
    abBase[1] = abBase[0] + 16384;

    const int tid  = threadIdx.x;
    const int lane = tid & 31;
    const int warp = tid >> 5;
    const int wm = warp & 1;
    const int wn = warp >> 1;

    int z, m0, mstep, colOff;
    if (ZMODE == 1)      { z = blockIdx.x & 3; colOff = 0;                      m0 = blockIdx.x >> 2; mstep = gridDim.x >> 2; }
    else if (ZMODE == 2) { z = 0;              colOff = (blockIdx.x & 1) * 128; m0 = blockIdx.x >> 1; mstep = gridDim.x >> 1; }
    else                 { z = 0;              colOff = 0;                      m0 = blockIdx.x;      mstep = gridDim.x; }

    const float* W    = p.W[ZMODE == 1 ? z : 0];
    const float* bias = p.B[ZMODE == 1 ? z : 0] + colOff;
    float*       C    = p.C[ZMODE == 1 ? z : 0];
    const int ldC = ldW;

    int mi_p = m0, kc_p = 0;
    int mi_c = m0, kc_c = 0;
    auto issueA = [&](int mi, int kc, int bi) {
        int rowBase = mi * 128;
        #pragma unroll
        for (int it = 0; it < 4; it++) {
            int idx = it * 256 + tid;
            int row = idx >> 3;
            int c   = idx & 7;
            int grow = rowBase + row;
            const float* src = A + (size_t)grow * K + kc * 32 + c * 4;
            unsigned dst = abBase[bi] + (row << 7) + ((c ^ (row & 7)) << 4);
            int sz = (grow < M) ? 16 : 0;
            asm volatile("cp.async.cg.shared.global [%0], [%1], 16, %2;"
                         :: "r"(dst), "l"(src), "r"(sz));
        }
    };
    auto adv = [](int& mi, int& kc, int step) {
        if (++kc == NCH) { kc = 0; mi += step; }
    };

    issueA(mi_p, kc_p, 0);
    adv(mi_p, kc_p, mstep);
    asm volatile("cp.async.commit_group;");

    // BN1 scale/shift computed locally from g_sums (replaces bnfin launch)
    if (BNB || BNADD) {
        if (tid < 128) {
            float mu  = g_sums[tid] / (float)NN;
            float var = g_sums[DD + tid] / (float)NN - mu * mu;
            float sc = bng[tid] * rsqrtf(var + EPSV);
            scale_s[tid] = sc;
            shift_s[tid] = bnbe[tid] - mu * sc;
        }
        __syncthreads();
    }

    #pragma unroll 4
    for (int it = 0; it < K / 8; it++) {
        int k  = it * 8 + (tid >> 5);
        int n0 = (tid & 31) * 4;
        float4 w = *(const float4*)(W + (size_t)k * ldW + colOff + n0);
        float s = BNB ? scale_s[k] : 1.f;
        float4 r;
        r.x = tf32r(w.x * s); r.y = tf32r(w.y * s);
        r.z = tf32r(w.z * s); r.w = tf32r(w.w * s);
        int kq = k >> 2, k3 = k & 3;
        int base = kq * 512 + k3 * 128 + (n0 & ~31) + ((n0 + 8 * k3) & 31);
        *(float4*)(Bs + base) = r;
    }
    if (tid < 128) {
        float b = bias[tid];
        if (BNB) {
            float a = 0.f;
            #pragma unroll 8
            for (int k = 0; k < K; k++)
                a += shift_s[k] * W[(size_t)k * ldW + colOff + tid];
            b += a;
        }
        bias_s[tid] = b;
    }
    __syncthreads();

    const int rl   = (lane & 7) + ((lane >> 3) & 1) * 8;
    const int cbit = lane >> 4;
    int innerj[4];
    #pragma unroll
    for (int j = 0; j < 4; j++)
        innerj[j] = ((j << 3) + (lane >> 2) + ((lane & 3) << 3)) & 31;

    float acc[4][4][4];
    int buf = 0;

    while (mi_c < MTILES) {
        if (mi_p < MTILES) {
            issueA(mi_p, kc_p, buf ^ 1);
            adv(mi_p, kc_p, mstep);
        }
        asm volatile("cp.async.commit_group;");
        asm volatile("cp.async.wait_group 1;");
        __syncthreads();

        if (kc_c == 0) {
            #pragma unroll
            for (int i = 0; i < 4; i++)
                #pragma unroll
                for (int j = 0; j < 4; j++)
                    #pragma unroll
                    for (int r = 0; r < 4; r++) acc[i][j][r] = 0.f;
        }

        const unsigned ab = abBase[buf];
        #pragma unroll
        for (int kt = 0; kt < 4; kt++) {
            unsigned af[4][4], bf[4][2];
            #pragma unroll
            for (int i = 0; i < 4; i++) {
                int mt = wm * 4 + i;
                unsigned addr = ab + ((mt * 16 + rl) << 7)
                              + ((((kt << 1) + cbit) ^ (lane & 7)) << 4);
                asm volatile("ldmatrix.sync.aligned.m8n8.x4.shared.b16 {%0,%1,%2,%3}, [%4];"
                             : "=r"(af[i][0]), "=r"(af[i][1]), "=r"(af[i][2]), "=r"(af[i][3])
                             : "r"(addr));
                #pragma unroll
                for (int q = 0; q < 4; q++)
                    asm("cvt.rna.tf32.f32 %0, %0;" : "+r"(af[i][q]));
            }
            int kq0 = (kc_c * 8 + kt * 2) * 512 + (lane & 3) * 128 + wn * 32;
            #pragma unroll
            for (int j = 0; j < 4; j++) {
                bf[j][0] = __float_as_uint(Bs[kq0 + innerj[j]]);
                bf[j][1] = __float_as_uint(Bs[kq0 + 512 + innerj[j]]);
            }
            #pragma unroll
            for (int i = 0; i < 4; i++)
                #pragma unroll
                for (int j = 0; j < 4; j++)
                    mma8(acc[i][j], af[i], bf[j]);
        }

        if (kc_c == NCH - 1) {
            int rowBase = mi_c * 128;
            #pragma unroll
            for (int j = 0; j < 4; j++) {
                int cl = wn * 32 + j * 8 + (lane & 3) * 2;
                int cg = colOff + cl;
                float2 bb = *(const float2*)&bias_s[cl];
                float sx = 0.f, qx = 0.f, sy = 0.f, qy = 0.f;
                #pragma unroll
                for (int i = 0; i < 4; i++) {
                    int r0 = rowBase + wm * 64 + i * 16 + (lane >> 2);
                    #pragma unroll
                    for (int hh = 0; hh < 2; hh++) {
                        int r = r0 + hh * 8;
                        if (r >= M) continue;
                        float2 o;
                        o.x = acc[i][j][hh * 2 + 0] + bb.x;
                        o.y = acc[i][j][hh * 2 + 1] + bb.y;
                        if (add) {
                            float2 ad = *(const float2*)(add + (size_t)r * ldC + cg);
                            if (BNADD) {
                                ad.x = ad.x * scale_s[cg]     + shift_s[cg];
                                ad.y = ad.y * scale_s[cg + 1] + shift_s[cg + 1];
                            }
                            o.x += ad.x; o.y += ad.y;
                        }
                        if (relu) { o.x = fmaxf(o.x, 0.f); o.y = fmaxf(o.y, 0.f); }
                        *(float2*)(C + (size_t)r * ldC + cg) = o;
                        if (BNST >= 0) {
                            sx += o.x; qx += o.x * o.x;
                            sy += o.y; qy += o.y * o.y;
                        }
                    }
                }
                if (BNST >= 0) {
                    #pragma unroll
                    for (int off = 16; off >= 4; off >>= 1) {
                        sx += __shfl_xor_sync(0xffffffffu, sx, off);
                        qx += __shfl_xor_sync(0xffffffffu, qx, off);
                        sy += __shfl_xor_sync(0xffffffffu, sy, off);
                        qy += __shfl_xor_sync(0xffffffffu, qy, off);
                    }
                    if ((lane >> 2) == 0) {
                        atomicAdd(&g_sums[BNST * 2 * DD + cg],          sx);
                        atomicAdd(&g_sums[BNST * 2 * DD + DD + cg],     qx);
                        atomicAdd(&g_sums[BNST * 2 * DD + cg + 1],      sy);
                        atomicAdd(&g_sums[BNST * 2 * DD + DD + cg + 1], qy);
                    }
                }
            }
        }
        __syncthreads();
        buf ^= 1;
        adv(mi_c, kc_c, mstep);
    }
}

// ---------------- BN2 apply (computes scale/shift per block from g_sums) -------
__global__ void bnapply_kernel(float* __restrict__ h,
                               const float* __restrict__ g, const float* __restrict__ be) {
    __shared__ float sc_s[DD], sh_s[DD];
    if (threadIdx.x < 128) {
        int c = threadIdx.x;
        float mu  = g_sums[2 * DD + c] / (float)NN;
        float var = g_sums[3 * DD + c] / (float)NN - mu * mu;
        float sc = g[c] * rsqrtf(var + EPSV);
        sc_s[c] = sc;
        sh_s[c] = be[c] - mu * sc;
    }
    __syncthreads();
    const int total = NN * DD / 4;
    for (int i = blockIdx.x * blockDim.x + threadIdx.x; i < total; i += gridDim.x * blockDim.x) {
        float4 vv = ((float4*)h)[i];
        int cb = (i & 31) << 2;
        float4 sc = *(const float4*)&sc_s[cb];
        float4 sh = *(const float4*)&sh_s[cb];
        vv.x = vv.x * sc.x + sh.x;
        vv.y = vv.y * sc.y + sh.y;
        vv.z = vv.z * sc.z + sh.z;
        vv.w = vv.w * sc.w + sh.w;
        ((float4*)h)[i] = vv;
    }
}

// ---------------- launch ----------------
extern "C" void kernel_launch(void* const* d_in, const int* in_sizes, int n_in,
                              void* d_out, int out_size)
{
    const float* x  = (const float*)d_in[0];
    const int*   ei = (const int*)  d_in[1];
    const float *Wq = (const float*)d_in[2],  *bq = (const float*)d_in[3];
    const float *Wk = (const float*)d_in[4],  *bk = (const float*)d_in[5];
    const float *Wv = (const float*)d_in[6],  *bv = (const float*)d_in[7];
    const float *Ws = (const float*)d_in[8],  *bs = (const float*)d_in[9];
    const float *WO = (const float*)d_in[10], *bO = (const float*)d_in[11];
    const float *W1 = (const float*)d_in[12], *b1 = (const float*)d_in[13];
    const float *W2 = (const float*)d_in[14], *b2 = (const float*)d_in[15];
    const float *g1 = (const float*)d_in[16], *be1 = (const float*)d_in[17];
    const float *g2 = (const float*)d_in[18], *be2 = (const float*)d_in[19];
    float* out = (float*)d_out;

    const int* src = ei;
    const int* dst = ei + EE;

    float *q, *k, *v, *sp, *h, *t;
    cudaGetSymbolAddress((void**)&q,  g_q);
    cudaGetSymbolAddress((void**)&k,  g_k);
    cudaGetSymbolAddress((void**)&v,  g_v);
    cudaGetSymbolAddress((void**)&sp, g_sp);
    cudaGetSymbolAddress((void**)&h,  g_h);
    cudaGetSymbolAddress((void**)&t,  g_t);

    const int SM2 = 2 * 64 * 128 * 4 + 32768 + 1536;   // KC=2: 2 CTAs/SM
    const int SM4 = 4 * 64 * 128 * 4 + 32768 + 1536;   // KC=4: 1 CTA/SM
    cudaFuncSetAttribute(gemm_tc<2,1,0,0,-1>, cudaFuncAttributeMaxDynamicSharedMemorySize, SM2);
    cudaFuncSetAttribute(gemm_tc<2,0,0,0,0>,  cudaFuncAttributeMaxDynamicSharedMemorySize, SM2);
    cudaFuncSetAttribute(gemm_tc<2,2,1,0,-1>, cudaFuncAttributeMaxDynamicSharedMemorySize, SM2);
    cudaFuncSetAttribute(gemm_tc<4,0,0,1,1>,  cudaFuncAttributeMaxDynamicSharedMemorySize, SM4);

    cudaStream_t s1;
    cudaEvent_t ev0, ev1;
    cudaStreamCreateWithFlags(&s1, cudaStreamNonBlocking);
    cudaEventCreateWithFlags(&ev0, cudaEventDisableTiming);
    cudaEventCreateWithFlags(&ev1, cudaEventDisableTiming);

    // ---- fork: CSR build (+ g_sums zeroing) on s1, QKVS GEMM on main.
    cudaEventRecord(ev0, 0);
    cudaStreamWaitEvent(s1, ev0, 0);
    zero_kernel<<<(NN + 255) / 256, 256, 0, s1>>>();   // launch 1
    hist_kernel<<<512, 256, 0, s1>>>(dst);             // launch 2
    scanA_kernel<<<SCANB, 1024, 0, s1>>>();            // launch 3

    // fused Q/K/V/S projections (main stream) — launch 4 (profiled)
    {
        P4 p;
        p.W[0] = Wq; p.B[0] = bq; p.C[0] = q;
        p.W[1] = Wk; p.B[1] = bk; p.C[1] = k;
        p.W[2] = Wv; p.B[2] = bv; p.C[2] = v;
        p.W[3] = Ws; p.B[3] = bs; p.C[3] = sp;
        gemm_tc<2,1,0,0,-1><<<296, 256, SM2>>>(x, p, nullptr, nullptr, nullptr, NN, 128, 0);
    }

    scanB_kernel<<<SCANB, 1024, 0, s1>>>();            // launch 5
    scatter_kernel<<<512, 256, 0, s1>>>(src, dst);     // launch 6
    cudaEventRecord(ev1, s1);

    // ---- join ----
    cudaStreamWaitEvent(0, ev1, 0);

    // attention (pairwise online softmax; writes agg + sp into sp)
    attn_kernel<<<(NN * 32 + 255) / 256, 256>>>(q, k, v, sp);

    // h = sp @ WO + bO + x, fused BN1 stats
    {
        P4 p = {};
        p.W[0] = WO; p.B[0] = bO; p.C[0] = h;
        gemm_tc<2,0,0,0,0><<<296, 256, SM2>>>(sp, p, x, nullptr, nullptr, NN, 128, 0);
    }

    // FFN1: t = relu(BN1(h) @ W1 + b1)   (BN1 scale/shift computed in-block)
    {
        P4 p = {};
        p.W[0] = W1; p.B[0] = b1; p.C[0] = t;
        gemm_tc<2,2,1,0,-1><<<296, 256, SM2>>>(h, p, nullptr, g1, be1, NN, 256, 1);
    }
    // FFN2: out = t @ W2 + b2 + BN1(h), fused BN2 stats
    {
        P4 p = {};
        p.W[0] = W2; p.B[0] = b2; p.C[0] = out;
        gemm_tc<4,0,0,1,1><<<148, 256, SM4>>>(t, p, h, g1, be1, NN, 128, 0);
    }

    // BN2 apply (scale/shift computed in-block)
    bnapply_kernel<<<512, 256>>>(out, g2, be2);
}